// round 12
// baseline (speedup 1.0000x reference)
#include <cuda_runtime.h>
#include <cstdint>

// PolicyEncoder gather-sum:
// out[n, :] = bias + w_state0[obs0[n]] + w_state1[obs1[n]] + w_act0[act0[n]] + w_act1[act1[n]]
// N = 262144 rows, D = 128 floats per row.
//
// R12: half-row warps (float2 lanes) to cut pipeline register cost and raise
// occupancy to 40 warps/SM while keeping R5's proven 2-stage gather pipeline.
//  - Each warp owns a HALF row: 32 lanes x float2 (8B) = 256B.
//  - 2-stage pipeline: per iteration, issue indices for half-row k+2 and
//    gathers for k+1, consume k (gathers issued one iteration earlier).
//  - grid = 148 SMs * 5 blocks * 8 warps = 5920 warps over 2N = 524288
//    half-rows (~88 iterations each). __launch_bounds__(256,5) -> <=51 regs.
//  - Streaming stores (__stcs), gathers via __ldg (act tables hit L1).

struct Idx { int i0, i1, i2, i3; };

__device__ __forceinline__ Idx load_idx(const int* __restrict__ o0,
                                        const int* __restrict__ o1,
                                        const int* __restrict__ a0,
                                        const int* __restrict__ a1, int r) {
    Idx x;
    x.i0 = __ldg(o0 + r);
    x.i1 = __ldg(o1 + r);
    x.i2 = __ldg(a0 + r);
    x.i3 = __ldg(a1 + r);
    return x;
}

__global__ void __launch_bounds__(256, 5)
policy_encoder_kernel(const int* __restrict__ obs0,
                      const int* __restrict__ obs1,
                      const int* __restrict__ act0,
                      const int* __restrict__ act1,
                      const float2* __restrict__ w0,   // [OBS0, 64] as float2
                      const float2* __restrict__ w1,
                      const float2* __restrict__ w2,
                      const float2* __restrict__ w3,
                      const float2* __restrict__ bias, // [64]
                      float2* __restrict__ out,        // [N, 64]
                      int nHalf)                        // 2 * N
{
    const int lane   = threadIdx.x & 31;
    const int gw     = (int)((blockIdx.x * blockDim.x + threadIdx.x) >> 5);
    const int stride = (int)((gridDim.x * blockDim.x) >> 5);

    if (gw >= nHalf) return;
    const int last = nHalf - 1;

    // half-row h -> row = h >> 1, column base = (h & 1) * 32 + lane (float2 units)
    // col for half-row h: coff(h) = (h & 1) * 32 + lane
    const float2 bEven = __ldg(bias + lane);        // half 0
    const float2 bOdd  = __ldg(bias + 32 + lane);   // half 1

    // ---- prologue: h0 indices + gathers, h1 indices ----
    Idx ic = load_idx(obs0, obs1, act0, act1, gw >> 1);
    int h1 = gw + stride;
    Idx in_ = load_idx(obs0, obs1, act0, act1, (h1 <= last ? h1 : last) >> 1);

    {
        const int c0 = (gw & 1) * 32 + lane;
        float2 g0 = __ldg(w0 + (size_t)ic.i0 * 64 + c0);
        float2 g1 = __ldg(w1 + (size_t)ic.i1 * 64 + c0);
        float2 g2 = __ldg(w2 + (size_t)ic.i2 * 64 + c0);
        float2 g3 = __ldg(w3 + (size_t)ic.i3 * 64 + c0);

        // ---- steady state ----
        for (int h = gw; h <= last; h += stride) {
            // indices for half-row h + 2*stride (clamped at tail)
            int hnn = h + 2 * stride;
            Idx inn = load_idx(obs0, obs1, act0, act1,
                               (hnn <= last ? hnn : last) >> 1);

            // gathers for half-row h + stride (indices arrived last iteration)
            int hn = h + stride; hn = hn <= last ? hn : last;
            const int cn = (hn & 1) * 32 + lane;
            float2 q0 = __ldg(w0 + (size_t)in_.i0 * 64 + cn);
            float2 q1 = __ldg(w1 + (size_t)in_.i1 * 64 + cn);
            float2 q2 = __ldg(w2 + (size_t)in_.i2 * 64 + cn);
            float2 q3 = __ldg(w3 + (size_t)in_.i3 * 64 + cn);

            // consume half-row h
            const float2 bb = (h & 1) ? bOdd : bEven;
            float2 res;
            res.x = bb.x + g0.x + g1.x + g2.x + g3.x;
            res.y = bb.y + g0.y + g1.y + g2.y + g3.y;
            __stcs(out + (size_t)h * 32 + lane, res);

            // rotate pipeline registers
            g0 = q0; g1 = q1; g2 = q2; g3 = q3;
            in_ = inn;
        }
    }
}

extern "C" void kernel_launch(void* const* d_in, const int* in_sizes, int n_in,
                              void* d_out, int out_size)
{
    const int*    obs0 = (const int*)d_in[0];
    const int*    obs1 = (const int*)d_in[1];
    const int*    act0 = (const int*)d_in[2];
    const int*    act1 = (const int*)d_in[3];
    const float2* w0   = (const float2*)d_in[4];
    const float2* w1   = (const float2*)d_in[5];
    const float2* w2   = (const float2*)d_in[6];
    const float2* w3   = (const float2*)d_in[7];
    const float2* bias = (const float2*)d_in[8];
    float2*       out  = (float2*)d_out;

    const int n = in_sizes[0];     // number of rows (N)
    const int threads = 256;       // 8 warps/block
    const int blocks  = 148 * 5;   // one exact wave at 5 blocks/SM

    policy_encoder_kernel<<<blocks, threads>>>(obs0, obs1, act0, act1,
                                               w0, w1, w2, w3, bias, out,
                                               2 * n);
}

// round 13
// speedup vs baseline: 1.1218x; 1.1218x over previous
#include <cuda_runtime.h>
#include <cstdint>

// PolicyEncoder gather-sum:
// out[n, :] = bias + w_state0[obs0[n]] + w_state1[obs1[n]] + w_act0[act0[n]] + w_act1[act1[n]]
// N = 262144 rows, D = 128 floats per row.
//
// R13 = R5 shape (warp-per-row float4 lanes, grid-stride over rows,
// 148*4-block exact wave, broadcast index loads, __stcs stores) with the
// gathers moved to a 3-deep cp.async smem ring:
//  - Each lane cp.async's its own 16B of each table row into smem and later
//    reads back the same 16B -> no intra-warp sync needed, only wait_group.
//  - 12 gathers (3 rows x 4 tables) permanently in flight per warp, with no
//    register cost (regs ~36 vs 64), tripling per-SM outstanding gather bytes
//    to feed HBM bank-level parallelism.
//  - smem: 8 warps * 3 stages * 4 tables * 512B = 48KB per block.

#define PD 3                     // pipeline depth (stages in the smem ring)

__device__ __forceinline__ void cp16(uint32_t smem_dst, const void* gsrc) {
    asm volatile("cp.async.cg.shared.global [%0], [%1], 16;"
                 :: "r"(smem_dst), "l"(gsrc));
}
__device__ __forceinline__ void cp_commit() {
    asm volatile("cp.async.commit_group;");
}
__device__ __forceinline__ void cp_wait_allbutN() {
    asm volatile("cp.async.wait_group %0;" :: "n"(PD - 1));
}

__global__ void __launch_bounds__(256, 4)
policy_encoder_kernel(const int* __restrict__ obs0,
                      const int* __restrict__ obs1,
                      const int* __restrict__ act0,
                      const int* __restrict__ act1,
                      const float4* __restrict__ w0,   // [OBS0, 32] as float4
                      const float4* __restrict__ w1,
                      const float4* __restrict__ w2,
                      const float4* __restrict__ w3,
                      const float4* __restrict__ bias, // [32]
                      float4* __restrict__ out,        // [N, 32]
                      int n)
{
    extern __shared__ float4 smbuf[];   // [8 warps][PD][4 tables][32 lanes]

    const int lane   = threadIdx.x & 31;
    const int warpId = threadIdx.x >> 5;
    const int gw     = (int)((blockIdx.x * blockDim.x + threadIdx.x) >> 5);
    const int stride = (int)((gridDim.x * blockDim.x) >> 5);

    if (gw >= n) return;
    const int last = n - 1;

    // smem base (byte address) for this warp's ring; lane slot within a
    // table row is fixed = lane.
    uint32_t smBase;
    {
        const float4* p = smbuf + (size_t)warpId * (PD * 4 * 32) + lane;
        asm("{ .reg .u64 t; cvta.to.shared.u64 t, %1; cvt.u32.u64 %0, t; }"
            : "=r"(smBase) : "l"(p));
    }
    // stage s, table t slot address: smBase + (s*4 + t) * 32 * 16 bytes
    const uint32_t STAGE_BYTES = 4 * 32 * sizeof(float4);
    const uint32_t TABLE_BYTES = 32 * sizeof(float4);

    const float4 b = __ldg(bias + lane);

    // ---- prologue: fill PD stages ----
    #pragma unroll
    for (int d = 0; d < PD; ++d) {
        int r = gw + d * stride; r = r <= last ? r : last;
        const int i0 = __ldg(obs0 + r);
        const int i1 = __ldg(obs1 + r);
        const int i2 = __ldg(act0 + r);
        const int i3 = __ldg(act1 + r);
        const uint32_t sb = smBase + d * STAGE_BYTES;
        cp16(sb + 0 * TABLE_BYTES, w0 + (size_t)i0 * 32 + lane);
        cp16(sb + 1 * TABLE_BYTES, w1 + (size_t)i1 * 32 + lane);
        cp16(sb + 2 * TABLE_BYTES, w2 + (size_t)i2 * 32 + lane);
        cp16(sb + 3 * TABLE_BYTES, w3 + (size_t)i3 * 32 + lane);
        cp_commit();
    }

    // ---- steady state ----
    int stage = 0;
    for (int r = gw; r <= last; r += stride) {
        // oldest group (this stage) complete; PD-1 still allowed in flight
        cp_wait_allbutN();

        const uint32_t sb = smBase + stage * STAGE_BYTES;
        // each lane reads back exactly the 16B it copied -> no syncwarp
        float4 g0, g1, g2, g3;
        asm volatile("ld.shared.v4.f32 {%0,%1,%2,%3}, [%4];"
                     : "=f"(g0.x), "=f"(g0.y), "=f"(g0.z), "=f"(g0.w)
                     : "r"(sb + 0 * TABLE_BYTES));
        asm volatile("ld.shared.v4.f32 {%0,%1,%2,%3}, [%4];"
                     : "=f"(g1.x), "=f"(g1.y), "=f"(g1.z), "=f"(g1.w)
                     : "r"(sb + 1 * TABLE_BYTES));
        asm volatile("ld.shared.v4.f32 {%0,%1,%2,%3}, [%4];"
                     : "=f"(g2.x), "=f"(g2.y), "=f"(g2.z), "=f"(g2.w)
                     : "r"(sb + 2 * TABLE_BYTES));
        asm volatile("ld.shared.v4.f32 {%0,%1,%2,%3}, [%4];"
                     : "=f"(g3.x), "=f"(g3.y), "=f"(g3.z), "=f"(g3.w)
                     : "r"(sb + 3 * TABLE_BYTES));

        float4 res;
        res.x = b.x + g0.x + g1.x + g2.x + g3.x;
        res.y = b.y + g0.y + g1.y + g2.y + g3.y;
        res.z = b.z + g0.z + g1.z + g2.z + g3.z;
        res.w = b.w + g0.w + g1.w + g2.w + g3.w;
        __stcs(out + (size_t)r * 32 + lane, res);

        // refill this stage with row r + PD*stride
        int rn = r + PD * stride; rn = rn <= last ? rn : last;
        const int j0 = __ldg(obs0 + rn);
        const int j1 = __ldg(obs1 + rn);
        const int j2 = __ldg(act0 + rn);
        const int j3 = __ldg(act1 + rn);
        cp16(sb + 0 * TABLE_BYTES, w0 + (size_t)j0 * 32 + lane);
        cp16(sb + 1 * TABLE_BYTES, w1 + (size_t)j1 * 32 + lane);
        cp16(sb + 2 * TABLE_BYTES, w2 + (size_t)j2 * 32 + lane);
        cp16(sb + 3 * TABLE_BYTES, w3 + (size_t)j3 * 32 + lane);
        cp_commit();

        stage = stage + 1 == PD ? 0 : stage + 1;
    }
}

extern "C" void kernel_launch(void* const* d_in, const int* in_sizes, int n_in,
                              void* d_out, int out_size)
{
    const int*    obs0 = (const int*)d_in[0];
    const int*    obs1 = (const int*)d_in[1];
    const int*    act0 = (const int*)d_in[2];
    const int*    act1 = (const int*)d_in[3];
    const float4* w0   = (const float4*)d_in[4];
    const float4* w1   = (const float4*)d_in[5];
    const float4* w2   = (const float4*)d_in[6];
    const float4* w3   = (const float4*)d_in[7];
    const float4* bias = (const float4*)d_in[8];
    float4*       out  = (float4*)d_out;

    const int n = in_sizes[0];     // number of rows (N)
    const int threads = 256;       // 8 warps/block
    const int blocks  = 148 * 4;   // one exact wave at 4 blocks/SM

    const int smemBytes = 8 * PD * 4 * 32 * sizeof(float4);   // 48KB

    cudaFuncSetAttribute(policy_encoder_kernel,
                         cudaFuncAttributeMaxDynamicSharedMemorySize, smemBytes);
    policy_encoder_kernel<<<blocks, threads, smemBytes>>>(
        obs0, obs1, act0, act1, w0, w1, w2, w3, bias, out, n);
}

// round 14
// speedup vs baseline: 1.3692x; 1.2206x over previous
#include <cuda_runtime.h>
#include <cstdint>

// PolicyEncoder gather-sum:
// out[n, :] = bias + w_state0[obs0[n]] + w_state1[obs1[n]] + w_act0[act0[n]] + w_act1[act1[n]]
// N = 262144 rows, D = 128 floats per row.
//
// R14 = R5 (persistent warp-per-row, 2-stage pipeline, grid-stride,
// broadcast index loads, __stcs streaming stores) with the loop reordered
// consume-then-issue so the next-row gather payload reuses the current-row
// registers (saves 16 regs -> fits 5 blocks/SM = 40 warps/SM instead of 30).
// Lookahead is still ~0.9 iteration (~1400 cyc) >> DRAM latency.

struct Idx { int i0, i1, i2, i3; };

__device__ __forceinline__ Idx load_idx(const int* __restrict__ o0,
                                        const int* __restrict__ o1,
                                        const int* __restrict__ a0,
                                        const int* __restrict__ a1, int r) {
    Idx x;
    x.i0 = __ldg(o0 + r);
    x.i1 = __ldg(o1 + r);
    x.i2 = __ldg(a0 + r);
    x.i3 = __ldg(a1 + r);
    return x;
}

__global__ void __launch_bounds__(256, 5)
policy_encoder_kernel(const int* __restrict__ obs0,
                      const int* __restrict__ obs1,
                      const int* __restrict__ act0,
                      const int* __restrict__ act1,
                      const float4* __restrict__ w0,   // [OBS0, 32] as float4
                      const float4* __restrict__ w1,
                      const float4* __restrict__ w2,
                      const float4* __restrict__ w3,
                      const float4* __restrict__ bias, // [32]
                      float4* __restrict__ out,        // [N, 32]
                      int n)
{
    const int lane   = threadIdx.x & 31;
    const int gw     = (int)((blockIdx.x * blockDim.x + threadIdx.x) >> 5);
    const int stride = (int)((gridDim.x * blockDim.x) >> 5);

    if (gw >= n) return;

    const float4 b = __ldg(bias + lane);
    const int last = n - 1;

    // ---- prologue ----
    // gathers for row gw in flight; indices for row gw+stride prefetched.
    Idx ic = load_idx(obs0, obs1, act0, act1, gw);
    int r1 = gw + stride;
    Idx in_ = load_idx(obs0, obs1, act0, act1, r1 <= last ? r1 : last);

    float4 g0 = __ldg(w0 + (size_t)ic.i0 * 32 + lane);
    float4 g1 = __ldg(w1 + (size_t)ic.i1 * 32 + lane);
    float4 g2 = __ldg(w2 + (size_t)ic.i2 * 32 + lane);
    float4 g3 = __ldg(w3 + (size_t)ic.i3 * 32 + lane);

    // ---- steady state: consume row r, THEN issue row r+stride into g ----
    for (int r = gw; r <= last; r += stride) {
        // indices for row r + 2*stride (issued early; cheap broadcast loads)
        int rnn = r + 2 * stride;
        Idx inn = load_idx(obs0, obs1, act0, act1, rnn <= last ? rnn : last);

        // consume row r (gathers issued one iteration ago)
        float4 res;
        res.x = b.x + g0.x + g1.x + g2.x + g3.x;
        res.y = b.y + g0.y + g1.y + g2.y + g3.y;
        res.z = b.z + g0.z + g1.z + g2.z + g3.z;
        res.w = b.w + g0.w + g1.w + g2.w + g3.w;
        __stcs(out + (size_t)r * 32 + lane, res);

        // issue gathers for row r + stride into the SAME registers
        g0 = __ldg(w0 + (size_t)in_.i0 * 32 + lane);
        g1 = __ldg(w1 + (size_t)in_.i1 * 32 + lane);
        g2 = __ldg(w2 + (size_t)in_.i2 * 32 + lane);
        g3 = __ldg(w3 + (size_t)in_.i3 * 32 + lane);

        in_ = inn;
    }
}

extern "C" void kernel_launch(void* const* d_in, const int* in_sizes, int n_in,
                              void* d_out, int out_size)
{
    const int*    obs0 = (const int*)d_in[0];
    const int*    obs1 = (const int*)d_in[1];
    const int*    act0 = (const int*)d_in[2];
    const int*    act1 = (const int*)d_in[3];
    const float4* w0   = (const float4*)d_in[4];
    const float4* w1   = (const float4*)d_in[5];
    const float4* w2   = (const float4*)d_in[6];
    const float4* w3   = (const float4*)d_in[7];
    const float4* bias = (const float4*)d_in[8];
    float4*       out  = (float4*)d_out;

    const int n = in_sizes[0];     // number of rows (N)
    const int threads = 256;       // 8 warps/block
    const int blocks  = 148 * 5;   // one exact wave at 5 blocks/SM

    policy_encoder_kernel<<<blocks, threads>>>(obs0, obs1, act0, act1,
                                               w0, w1, w2, w3, bias, out, n);
}